// round 2
// baseline (speedup 1.0000x reference)
#include <cuda_runtime.h>
#include <cstdint>

// ============================================================================
// ShiftConv as gather-GEMM, tf32 mma.sync (sm_80+ PTX -> works on sm_103):
//   out[n,d,y,x] = sum_c x[n,c,y+sh[c],x+sw[c]] * W[c,d] + bias[d]
// M = 32*64*64 = 131072 (pixels), K = 256 (C_in), N = 256 (C_out)
// CTA tile 128x128, K chunk 32, 8 warps (warp tile 64x32), double-buffered.
// ============================================================================

#define CIN   256
#define NOUT  256
#define HW    4096
#define PITCH 136            // floats per smem row (128 + 8 pad: conflict-free)
#define ABUF  (32 * PITCH)   // 4352 floats per A/B stage buffer

__device__ float g_wt[CIN * NOUT];   // tf32-rounded weight, [k][n] layout

static __device__ __forceinline__ uint32_t f2tf32(float f) {
    uint32_t u;
    asm("cvt.rna.tf32.f32 %0, %1;" : "=r"(u) : "f"(f));
    return u;
}

// --- prep: round weights to tf32 once (W is already [C_in][C_out] = [k][n]) ---
__global__ void round_w_kernel(const float* __restrict__ w) {
    int i = (blockIdx.x * 256 + threadIdx.x) * 4;
    float4 v = *reinterpret_cast<const float4*>(w + i);
    float4 r;
    r.x = __uint_as_float(f2tf32(v.x));
    r.y = __uint_as_float(f2tf32(v.y));
    r.z = __uint_as_float(f2tf32(v.z));
    r.w = __uint_as_float(f2tf32(v.w));
    *reinterpret_cast<float4*>(g_wt + i) = r;
}

static __device__ __forceinline__ void mma_tf32(float* c, const uint32_t* a,
                                                const uint32_t* b) {
    asm volatile(
        "mma.sync.aligned.m16n8k8.row.col.f32.tf32.tf32.f32 "
        "{%0,%1,%2,%3}, {%4,%5,%6,%7}, {%8,%9}, {%0,%1,%2,%3};"
        : "+f"(c[0]), "+f"(c[1]), "+f"(c[2]), "+f"(c[3])
        : "r"(a[0]), "r"(a[1]), "r"(a[2]), "r"(a[3]), "r"(b[0]), "r"(b[1]));
}

static __device__ __forceinline__ void cp_async16(uint32_t dst, const void* src) {
    asm volatile("cp.async.ca.shared.global [%0], [%1], 16;"
                 :: "r"(dst), "l"(src) : "memory");
}

// ============================================================================
__global__ __launch_bounds__(256, 2) void shiftconv_mma(
    const float* __restrict__ x,
    const float* __restrict__ bias,
    const int* __restrict__ shift_h,
    const int* __restrict__ shift_w,
    float* __restrict__ out)
{
    extern __shared__ float smem[];
    float* As[2]   = {smem,            smem + ABUF};
    float* Bs[2]   = {smem + 2 * ABUF, smem + 3 * ABUF};
    int*   sh_s    = (int*)(smem + 4 * ABUF);
    int*   sw_s    = sh_s + 256;
    float* bias_s  = (float*)(sw_s + 256);

    int tid  = threadIdx.x;
    int lane = tid & 31;
    int wid  = tid >> 5;
    int warp_m = wid & 1;        // 2 warp-rows  (64 M each)
    int warp_n = wid >> 1;       // 4 warp-cols  (32 N each)

    sh_s[tid]   = shift_h[tid];
    sw_s[tid]   = shift_w[tid];
    bias_s[tid] = bias[tid];

    int m0   = blockIdx.x * 128;
    int n0   = blockIdx.y * 128;
    int nimg = m0 >> 12;
    int pix0 = m0 & 4095;
    const float* xb = x + (size_t)nimg * (CIN * HW);

    // per-thread gather coords: thread owns pixel mloc, channel half kg
    int mloc = tid & 127;
    int kg   = tid >> 7;
    int y    = (pix0 + mloc) >> 6;
    int xc   = mloc & 63;

    __syncthreads();   // sh_s/sw_s ready

    // ---- helpers (inlined) ----
    #define CP_B(c0, Bd) do {                                                  \
        uint32_t bd = (uint32_t)__cvta_generic_to_shared(Bd);                  \
        _Pragma("unroll")                                                      \
        for (int it = 0; it < 4; ++it) {                                       \
            int item = it * 256 + tid;                                         \
            int k_   = item >> 5;                                              \
            int seg  = item & 31;                                              \
            cp_async16(bd + (uint32_t)(k_ * PITCH + seg * 4) * 4,              \
                       g_wt + ((c0) + k_) * NOUT + n0 + seg * 4);              \
        }                                                                      \
        asm volatile("cp.async.commit_group;" ::: "memory");                   \
    } while (0)

    #define GATHER_A(c0, regs) do {                                            \
        _Pragma("unroll")                                                      \
        for (int i = 0; i < 16; ++i) {                                         \
            int c  = (c0) + kg * 16 + i;                                       \
            int sy = y + sh_s[c];                                              \
            int sx = xc + sw_s[c];                                             \
            float v = 0.f;                                                     \
            if ((unsigned)sy < 64u && (unsigned)sx < 64u)                      \
                v = __ldg(xb + (size_t)c * HW + sy * 64 + sx);                 \
            regs[i] = v;                                                       \
        }                                                                      \
    } while (0)

    #define STS_A(regs, Ad) do {                                               \
        _Pragma("unroll")                                                      \
        for (int i = 0; i < 16; ++i) {                                         \
            int k_ = kg * 16 + i;                                              \
            (Ad)[k_ * PITCH + mloc] = __uint_as_float(f2tf32(regs[i]));        \
        }                                                                      \
    } while (0)

    float acc[4][4][4];
    #pragma unroll
    for (int mt = 0; mt < 4; ++mt)
        #pragma unroll
        for (int nt = 0; nt < 4; ++nt)
            #pragma unroll
            for (int e = 0; e < 4; ++e) acc[mt][nt][e] = 0.f;

    // ---- prologue: stage chunk 0 ----
    {
        CP_B(0, Bs[0]);
        float regs[16];
        GATHER_A(0, regs);
        STS_A(regs, As[0]);
        asm volatile("cp.async.wait_group 0;" ::: "memory");
        __syncthreads();
    }

    // per-thread fragment base indices
    int a_k = lane & 3;                   // k within 8 (+4 for hi)
    int a_m = warp_m * 64 + (lane >> 2);  // m within CTA tile
    int b_n = warp_n * 32 + (lane >> 2);  // n within CTA tile

    // ---- mainloop: 8 K-chunks of 32 ----
    for (int s = 0; s < 8; ++s) {
        int b = s & 1;
        float pregs[16];
        if (s < 7) {
            CP_B((s + 1) * 32, Bs[b ^ 1]);
            GATHER_A((s + 1) * 32, pregs);   // LDGs in flight during compute
        }

        const uint32_t* Au = (const uint32_t*)As[b];
        const uint32_t* Bu = (const uint32_t*)Bs[b];
        #pragma unroll
        for (int ks = 0; ks < 4; ++ks) {
            int kb = ks * 8 + a_k;
            uint32_t afr[4][4], bfr[4][2];
            #pragma unroll
            for (int mt = 0; mt < 4; ++mt) {
                int mb = a_m + mt * 16;
                afr[mt][0] = Au[kb * PITCH + mb];
                afr[mt][1] = Au[kb * PITCH + mb + 8];
                afr[mt][2] = Au[(kb + 4) * PITCH + mb];
                afr[mt][3] = Au[(kb + 4) * PITCH + mb + 8];
            }
            #pragma unroll
            for (int nt = 0; nt < 4; ++nt) {
                bfr[nt][0] = Bu[kb * PITCH + b_n + nt * 8];
                bfr[nt][1] = Bu[(kb + 4) * PITCH + b_n + nt * 8];
            }
            #pragma unroll
            for (int mt = 0; mt < 4; ++mt)
                #pragma unroll
                for (int nt = 0; nt < 4; ++nt)
                    mma_tf32(acc[mt][nt], afr[mt], bfr[nt]);
        }

        if (s < 7) STS_A(pregs, As[b ^ 1]);
        asm volatile("cp.async.wait_group 0;" ::: "memory");
        __syncthreads();
    }

    // ---- epilogue: bias + store (out[n][d][pixel]) ----
    float* ob = out + (size_t)nimg * (NOUT * HW);
    #pragma unroll
    for (int mt = 0; mt < 4; ++mt) {
        int m_ = warp_m * 64 + mt * 16 + (lane >> 2);
        #pragma unroll
        for (int nt = 0; nt < 4; ++nt) {
            int d_ = n0 + warp_n * 32 + nt * 8 + 2 * (lane & 3);
            float b0 = bias_s[d_], b1 = bias_s[d_ + 1];
            size_t o = (size_t)d_ * HW + pix0 + m_;
            ob[o]          = acc[mt][nt][0] + b0;
            ob[o + HW]     = acc[mt][nt][1] + b1;
            ob[o + 8]      = acc[mt][nt][2] + b0;
            ob[o + HW + 8] = acc[mt][nt][3] + b1;
        }
    }

    #undef CP_B
    #undef GATHER_A
    #undef STS_A
}

// ============================================================================
extern "C" void kernel_launch(void* const* d_in, const int* in_sizes, int n_in,
                              void* d_out, int out_size) {
    const float* x      = (const float*)d_in[0];
    const float* weight = (const float*)d_in[1];
    const float* bias   = (const float*)d_in[2];
    const int*   sh     = (const int*)d_in[3];
    const int*   sw     = (const int*)d_in[4];
    float*       out    = (float*)d_out;

    static int smem_set = 0;
    const int smem_bytes = (4 * ABUF + 3 * 256) * 4;   // 72704 B
    if (!smem_set) {
        cudaFuncSetAttribute(shiftconv_mma,
                             cudaFuncAttributeMaxDynamicSharedMemorySize, smem_bytes);
        smem_set = 1;
    }

    round_w_kernel<<<64, 256>>>(weight);
    shiftconv_mma<<<dim3(1024, 2), 256, smem_bytes>>>(x, bias, sh, sw, out);
}

// round 3
// speedup vs baseline: 1.0737x; 1.0737x over previous
#include <cuda_runtime.h>
#include <cstdint>

// ============================================================================
// ShiftConv as gather-GEMM, tf32 mma.sync (sm_80+ PTX, runs on plain sm_103):
//   out[n,d,y,x] = sum_c x[n,c,y+sh[c],x+sw[c]] * W[c,d] + bias[d]
// M = 131072 pixels, K = 256, N = 256.
// CTA tile 128(M) x 256(N), 512 threads (16 warps, 2x8, warp tile 64x32),
// K chunked 8 x 32, double-buffered, float2-packed mma fragments in smem.
// ============================================================================

#define CIN   256
#define NOUT  256
#define HW    4096

// A stage: float2[4 ks][128 m][4 a]  (16 KB), swizzle a ^= (m>>2)&3
#define A_F2   2048
// B stage: float2[4 ks][256 n][4 a]  (32 KB), swizzle a ^= n&2 (pre-baked in gmem)
#define B_F2   4096

__device__ float2 g_wp[CIN * NOUT / 4 * 4];   // 65536 float2 = 512 KB, packed weight

static __device__ __forceinline__ uint32_t f2tf32(float f) {
    uint32_t u;
    asm("cvt.rna.tf32.f32 %0, %1;" : "=r"(u) : "f"(f));
    return u;
}

// --- prep: pack weight into per-chunk fragment-paired, pre-swizzled layout ---
// f2 index: s(8) | ks(4) | n(256) | j(4);  stored a = j ^ (n & 2)
// value = { tf32(W[s*32+ks*8+a][n]), tf32(W[s*32+ks*8+a+4][n]) }
__global__ void pack_w_kernel(const float* __restrict__ w) {
    int idx = blockIdx.x * 256 + threadIdx.x;     // 0 .. 65535
    int j  = idx & 3;
    int n  = (idx >> 2) & 255;
    int ks = (idx >> 10) & 3;
    int s  = idx >> 12;
    int a  = j ^ (n & 2);
    int k1 = s * 32 + ks * 8 + a;
    float2 v;
    v.x = __uint_as_float(f2tf32(w[k1 * NOUT + n]));
    v.y = __uint_as_float(f2tf32(w[(k1 + 4) * NOUT + n]));
    g_wp[idx] = v;
}

static __device__ __forceinline__ void mma_tf32(float* c, uint32_t a0, uint32_t a1,
                                                uint32_t a2, uint32_t a3,
                                                uint32_t b0, uint32_t b1) {
    asm volatile(
        "mma.sync.aligned.m16n8k8.row.col.f32.tf32.tf32.f32 "
        "{%0,%1,%2,%3}, {%4,%5,%6,%7}, {%8,%9}, {%0,%1,%2,%3};"
        : "+f"(c[0]), "+f"(c[1]), "+f"(c[2]), "+f"(c[3])
        : "r"(a0), "r"(a1), "r"(a2), "r"(a3), "r"(b0), "r"(b1));
}

static __device__ __forceinline__ void cp_async16(uint32_t dst, const void* src) {
    asm volatile("cp.async.ca.shared.global [%0], [%1], 16;"
                 :: "r"(dst), "l"(src) : "memory");
}

static __device__ __forceinline__ void lds64(uint32_t& lo, uint32_t& hi, uint32_t addr) {
    asm volatile("ld.shared.v2.b32 {%0,%1}, [%2];" : "=r"(lo), "=r"(hi) : "r"(addr));
}

static __device__ __forceinline__ void sts64(uint32_t addr, uint32_t lo, uint32_t hi) {
    asm volatile("st.shared.v2.b32 [%0], {%1,%2};" :: "r"(addr), "r"(lo), "r"(hi) : "memory");
}

// ============================================================================
__global__ __launch_bounds__(512, 1) void shiftconv_mma(
    const float* __restrict__ x,
    const float* __restrict__ bias,
    const int* __restrict__ shift_h,
    const int* __restrict__ shift_w,
    float* __restrict__ out)
{
    extern __shared__ float smem[];
    // [A0 f2 | A1 f2 | B0 f2 | B1 f2 | sh 256 | sw 256 | bias 256]
    float* A_s[2] = {smem,                      smem + 2 * A_F2};
    float* B_s[2] = {smem + 4 * A_F2,           smem + 4 * A_F2 + 2 * B_F2};
    int*   sh_s   = (int*)(smem + 4 * A_F2 + 4 * B_F2);
    int*   sw_s   = sh_s + 256;
    float* bias_s = (float*)(sw_s + 256);

    int tid  = threadIdx.x;
    int lane = tid & 31;
    int wid  = tid >> 5;
    int warp_m = wid & 1;        // 2 M-warps (64 rows each)
    int warp_n = wid >> 1;       // 8 N-warps (32 cols each)

    if (tid < 256) {
        sh_s[tid]   = shift_h[tid];
        sw_s[tid]   = shift_w[tid];
        bias_s[tid] = bias[tid];
    }

    int m0   = blockIdx.x * 128;
    int nimg = m0 >> 12;
    int pix0 = m0 & 4095;
    const float* xb = x + (size_t)nimg * (CIN * HW);

    // gather ownership: pixel mloc, channel-octet kg (8 channels each)
    int mloc = tid & 127;
    int kg   = tid >> 7;         // 0..3 == ks
    int y    = (pix0 + mloc) >> 6;
    int xc   = mloc & 63;
    int aswz = (mloc >> 2) & 3;  // A staging swizzle term

    uint32_t a_smem[2], b_smem[2];
    a_smem[0] = (uint32_t)__cvta_generic_to_shared(A_s[0]);
    a_smem[1] = (uint32_t)__cvta_generic_to_shared(A_s[1]);
    b_smem[0] = (uint32_t)__cvta_generic_to_shared(B_s[0]);
    b_smem[1] = (uint32_t)__cvta_generic_to_shared(B_s[1]);

    __syncthreads();

    // ---- staging helpers ----
    #define CP_B(s_, buf) do {                                                 \
        const float2* src = g_wp + (size_t)(s_) * B_F2;                        \
        _Pragma("unroll")                                                      \
        for (int it = 0; it < 4; ++it) {                                       \
            int g = it * 512 + tid;          /* 16B granule = 2 f2 */          \
            cp_async16(b_smem[buf] + (uint32_t)g * 16, src + g * 2);           \
        }                                                                      \
        asm volatile("cp.async.commit_group;" ::: "memory");                   \
    } while (0)

    #define GATHER_A(c0, regs) do {                                            \
        _Pragma("unroll")                                                      \
        for (int i = 0; i < 8; ++i) {                                          \
            int c  = (c0) + kg * 8 + i;                                        \
            int sy = y + sh_s[c];                                              \
            int sx = xc + sw_s[c];                                             \
            float v = 0.f;                                                     \
            if ((unsigned)sy < 64u && (unsigned)sx < 64u)                      \
                v = __ldg(xb + (size_t)c * HW + sy * 64 + sx);                 \
            regs[i] = v;                                                       \
        }                                                                      \
    } while (0)

    // STS.64 pairs {k, k+4}: f2 index = (kg*128 + mloc)*4 + (i ^ aswz)
    #define STS_A(regs, buf) do {                                              \
        uint32_t base = a_smem[buf] + (uint32_t)((kg * 128 + mloc) * 4) * 8;   \
        _Pragma("unroll")                                                      \
        for (int i = 0; i < 4; ++i)                                            \
            sts64(base + (uint32_t)(i ^ aswz) * 8,                             \
                  f2tf32(regs[i]), f2tf32(regs[i + 4]));                       \
    } while (0)

    float acc[4][4][4];
    #pragma unroll
    for (int mt = 0; mt < 4; ++mt)
        #pragma unroll
        for (int nt = 0; nt < 4; ++nt)
            #pragma unroll
            for (int e = 0; e < 4; ++e) acc[mt][nt][e] = 0.f;

    // ---- prologue: stage chunk 0 ----
    {
        CP_B(0, 0);
        float regs[8];
        GATHER_A(0, regs);
        STS_A(regs, 0);
        asm volatile("cp.async.wait_group 0;" ::: "memory");
        __syncthreads();
    }

    // fragment indices
    int fa   = lane & 3;                      // a_k
    int fmof = lane >> 2;                     // m / n offset within 8-run
    int fm0  = warp_m * 64 + fmof;            // A m base (mt*16 added)
    int fn0  = warp_n * 32 + fmof;            // B n base (nt*8 added)

    // ---- mainloop: 8 K-chunks of 32 ----
    for (int s = 0; s < 8; ++s) {
        int b = s & 1;
        float pregs[8];
        if (s < 7) {
            CP_B(s + 1, b ^ 1);
            GATHER_A((s + 1) * 32, pregs);    // LDGs overlap compute below
        }

        #pragma unroll
        for (int ks = 0; ks < 4; ++ks) {
            uint32_t afr[4][4], bfr[4][2];
            #pragma unroll
            for (int mt = 0; mt < 4; ++mt) {
                int m = fm0 + mt * 16;
                int sz = fa ^ ((m >> 2) & 3);
                uint32_t ab = a_smem[b] + (uint32_t)((ks * 128 + m) * 4 + sz) * 8;
                lds64(afr[mt][0], afr[mt][2], ab);                    // {k, k+4} @ m
                int m8 = m + 8;
                int sz8 = fa ^ ((m8 >> 2) & 3);
                uint32_t ab8 = a_smem[b] + (uint32_t)((ks * 128 + m8) * 4 + sz8) * 8;
                lds64(afr[mt][1], afr[mt][3], ab8);                   // {k, k+4} @ m+8
            }
            #pragma unroll
            for (int nt = 0; nt < 4; ++nt) {
                int n = fn0 + nt * 8;
                uint32_t bb = b_smem[b] + (uint32_t)((ks * 256 + n) * 4 + (fa ^ (n & 2))) * 8;
                lds64(bfr[nt][0], bfr[nt][1], bb);                    // {k, k+4} @ n
            }
            #pragma unroll
            for (int mt = 0; mt < 4; ++mt)
                #pragma unroll
                for (int nt = 0; nt < 4; ++nt)
                    mma_tf32(acc[mt][nt], afr[mt][0], afr[mt][1], afr[mt][2],
                             afr[mt][3], bfr[nt][0], bfr[nt][1]);
        }

        if (s < 7) STS_A(pregs, b ^ 1);
        asm volatile("cp.async.wait_group 0;" ::: "memory");
        __syncthreads();
    }

    // ---- epilogue: bias + store out[n][d][pixel] ----
    float* ob = out + (size_t)nimg * (NOUT * HW);
    #pragma unroll
    for (int mt = 0; mt < 4; ++mt) {
        int m_ = warp_m * 64 + mt * 16 + (lane >> 2);
        #pragma unroll
        for (int nt = 0; nt < 4; ++nt) {
            int d_ = warp_n * 32 + nt * 8 + 2 * (lane & 3);
            float b0 = bias_s[d_], b1 = bias_s[d_ + 1];
            size_t o = (size_t)d_ * HW + pix0 + m_;
            ob[o]          = acc[mt][nt][0] + b0;
            ob[o + HW]     = acc[mt][nt][1] + b1;
            ob[o + 8]      = acc[mt][nt][2] + b0;
            ob[o + HW + 8] = acc[mt][nt][3] + b1;
        }
    }

    #undef CP_B
    #undef GATHER_A
    #undef STS_A
}

// ============================================================================
extern "C" void kernel_launch(void* const* d_in, const int* in_sizes, int n_in,
                              void* d_out, int out_size) {
    const float* x      = (const float*)d_in[0];
    const float* weight = (const float*)d_in[1];
    const float* bias   = (const float*)d_in[2];
    const int*   sh     = (const int*)d_in[3];
    const int*   sw     = (const int*)d_in[4];
    float*       out    = (float*)d_out;

    // A: 2*16KB, B: 2*32KB, tables: 3KB
    const int smem_bytes = (4 * A_F2 + 4 * B_F2) * 8 + 3 * 256 * 4;   // 101376
    static int smem_set = 0;
    if (!smem_set) {
        cudaFuncSetAttribute(shiftconv_mma,
                             cudaFuncAttributeMaxDynamicSharedMemorySize, smem_bytes);
        smem_set = 1;
    }

    pack_w_kernel<<<256, 256>>>(weight);
    shiftconv_mma<<<1024, 512, smem_bytes>>>(x, bias, sh, sw, out);
}